// round 8
// baseline (speedup 1.0000x reference)
#include <cuda_runtime.h>
#include <cuda_bf16.h>

// WeightedAverage: 3x3 local softmax over L-channel diffs, weighted average
// of a/b channels. x_lab [N,3,512,512] fp32 -> out [N,2,512,512] fp32.
//
// R8: scalar weight math (no pack/unpack round-trips), packed FFMA2 only on
// the a/b accumulate chains, pow-2 halo-load indexing (no magic division),
// explicit 32-bit shared-memory addressing.

#define H 512
#define W 512
#define TX 32
#define TY 8
#define TILE_W 128
#define TILE_H 8
#define HROWS 10
#define SROW 132
#define SCH (HROWS * SROW)     // 1320 floats per channel
#define PLANE (H * W)

typedef unsigned long long u64;
typedef unsigned int u32;

__device__ __forceinline__ u64 PK(float lo, float hi) {
    u64 r; asm("mov.b64 %0,{%1,%2};" : "=l"(r) : "f"(lo), "f"(hi)); return r;
}
__device__ __forceinline__ void UPK(float& lo, float& hi, u64 v) {
    asm("mov.b64 {%0,%1},%2;" : "=f"(lo), "=f"(hi) : "l"(v));
}
__device__ __forceinline__ u64 ADD2(u64 a, u64 b) {
    u64 r; asm("add.rn.f32x2 %0,%1,%2;" : "=l"(r) : "l"(a), "l"(b)); return r;
}
__device__ __forceinline__ u64 MUL2(u64 a, u64 b) {
    u64 r; asm("mul.rn.f32x2 %0,%1,%2;" : "=l"(r) : "l"(a), "l"(b)); return r;
}
__device__ __forceinline__ u64 FMA2(u64 a, u64 b, u64 c) {
    u64 r; asm("fma.rn.f32x2 %0,%1,%2,%3;" : "=l"(r) : "l"(a), "l"(b), "l"(c)); return r;
}
__device__ __forceinline__ float EX2(float x) {
    float r; asm("ex2.approx.f32 %0,%1;" : "=f"(r) : "f"(x)); return r;
}
__device__ __forceinline__ float RCP(float x) {
    float r; asm("rcp.approx.f32 %0,%1;" : "=f"(r) : "f"(x)); return r;
}

// w = exp(-(l-lc)^2), scalar: FADD + FMUL + FMUL(imm) + MUFU
__device__ __forceinline__ float WGT(float l, float lc) {
    float d = l - lc;
    return EX2(d * d * (-1.4426950408889634f));
}

// load 6 consecutive floats from shared (16B-aligned u32 address)
__device__ __forceinline__ void lds6(float* d, u32 a) {
    asm volatile("ld.shared.v4.f32 {%0,%1,%2,%3},[%6];\n\t"
                 "ld.shared.v2.f32 {%4,%5},[%6+16];"
                 : "=f"(d[0]), "=f"(d[1]), "=f"(d[2]), "=f"(d[3]),
                   "=f"(d[4]), "=f"(d[5])
                 : "r"(a));
}

__global__ __launch_bounds__(256, 5) void wavg_kernel(
    const float* __restrict__ x, float* __restrict__ out)
{
    __shared__ __align__(16) float sm[3 * SCH];

    u32 smb;
    asm("{ .reg .u64 t; cvta.to.shared.u64 t, %1; cvt.u32.u64 %0, t; }"
        : "=r"(smb) : "l"(sm));

    const int n  = blockIdx.z;
    const int x0 = blockIdx.x * TILE_W;
    const int y0 = blockIdx.y * TILE_H;
    const int tid = threadIdx.y * TX + threadIdx.x;
    const float* base = x + n * 3 * PLANE;     // fits in int offsets

    // ---- halo load: interior (always x-in-range, pow-2 indexing) ----
    {
        const int k = tid & 31;                // float4 chunk 0..31
        const int rbase = tid >> 5;            // 0..7
        const float* gp = base + x0 + 4 * k;

        #pragma unroll
        for (int pass = 0; pass < 4; pass++) {
            int rowid = rbase + pass * 8;      // 0..31
            if (rowid < 30) {
                int c, r;
                if (rowid < 10)      { c = 0; r = rowid; }
                else if (rowid < 20) { c = 1; r = rowid - 10; }
                else                 { c = 2; r = rowid - 20; }
                int gy = y0 + r - 1;
                float4 v = make_float4(0.f, 0.f, 0.f, 0.f);
                if ((unsigned)gy < (unsigned)H)
                    v = *(const float4*)(gp + c * PLANE + gy * W);
                u32 sa = smb + ((c * SCH + r * SROW + 4 * k + 1) << 2);
                asm volatile("st.shared.f32 [%0], %1;\n\t"
                             "st.shared.f32 [%0+4], %2;\n\t"
                             "st.shared.f32 [%0+8], %3;\n\t"
                             "st.shared.f32 [%0+12], %4;"
                             :: "r"(sa), "f"(v.x), "f"(v.y), "f"(v.z), "f"(v.w)
                             : "memory");
            }
        }
        // edge columns s=0 (gx=x0-1) and s=129 (gx=x0+128): 60 loads
        if (tid < 60) {
            int rowid = tid >> 1;              // 0..29
            int e = tid & 1;
            int c, r;
            if (rowid < 10)      { c = 0; r = rowid; }
            else if (rowid < 20) { c = 1; r = rowid - 10; }
            else                 { c = 2; r = rowid - 20; }
            int gy = y0 + r - 1;
            int gx = e ? (x0 + 128) : (x0 - 1);
            float v = 0.f;
            if ((unsigned)gy < (unsigned)H && (unsigned)gx < (unsigned)W)
                v = base[c * PLANE + gy * W + gx];
            u32 sa = smb + ((c * SCH + r * SROW + (e ? 129 : 0)) << 2);
            asm volatile("st.shared.f32 [%0], %1;" :: "r"(sa), "f"(v) : "memory");
        }
    }
    __syncthreads();

    const int tx = threadIdx.x, ty = threadIdx.y;
    // base smem byte address of window row 0, this thread's column block
    const u32 rb = smb + ((ty * SROW + 4 * tx) << 2);
    const u32 RSTRIDE = SROW << 2;             // 528 bytes per row
    const u32 CSTRIDE = SCH << 2;              // 5280 bytes per channel

    float l[6], a[6], b[6];
    u64 den0, den1, wa0, wa1, wb0, wb1;
    float lc0, lc1, lc2, lc3;

    // ---- center window row (row ty+1): yields lc, center tap w==1 ----
    {
        lds6(l, rb + RSTRIDE);
        lc0 = l[1]; lc1 = l[2]; lc2 = l[3]; lc3 = l[4];
        float e00 = WGT(l[0], lc0), e10 = WGT(l[1], lc1);
        float e20 = WGT(l[2], lc2), e30 = WGT(l[3], lc3);
        float e02 = WGT(l[2], lc0), e12 = WGT(l[3], lc1);
        float e22 = WGT(l[4], lc2), e32 = WGT(l[5], lc3);
        u64 wA0 = PK(e00, e10), wA2 = PK(e02, e12);
        u64 wB0 = PK(e20, e30), wB2 = PK(e22, e32);
        const u64 one2 = PK(1.0f, 1.0f);
        den0 = ADD2(one2, ADD2(wA0, wA2));
        den1 = ADD2(one2, ADD2(wB0, wB2));

        lds6(a, rb + RSTRIDE + CSTRIDE);
        wa0 = FMA2(wA0, PK(a[0], a[1]), FMA2(wA2, PK(a[2], a[3]), PK(a[1], a[2])));
        wa1 = FMA2(wB0, PK(a[2], a[3]), FMA2(wB2, PK(a[4], a[5]), PK(a[3], a[4])));

        lds6(b, rb + RSTRIDE + 2 * CSTRIDE);
        wb0 = FMA2(wA0, PK(b[0], b[1]), FMA2(wA2, PK(b[2], b[3]), PK(b[1], b[2])));
        wb1 = FMA2(wB0, PK(b[2], b[3]), FMA2(wB2, PK(b[4], b[5]), PK(b[3], b[4])));
    }

    // ---- rows above (ty) and below (ty+2): full 3 taps ----
    #pragma unroll
    for (int rr = 0; rr <= 2; rr += 2) {
        const u32 ra = rb + (u32)rr * RSTRIDE;
        lds6(l, ra);
        float e00 = WGT(l[0], lc0), e10 = WGT(l[1], lc1);
        float e20 = WGT(l[2], lc2), e30 = WGT(l[3], lc3);
        float e01 = WGT(l[1], lc0), e11 = WGT(l[2], lc1);
        float e21 = WGT(l[3], lc2), e31 = WGT(l[4], lc3);
        float e02 = WGT(l[2], lc0), e12 = WGT(l[3], lc1);
        float e22 = WGT(l[4], lc2), e32 = WGT(l[5], lc3);
        u64 wA0 = PK(e00, e10), wA1 = PK(e01, e11), wA2 = PK(e02, e12);
        u64 wB0 = PK(e20, e30), wB1 = PK(e21, e31), wB2 = PK(e22, e32);
        den0 = ADD2(den0, ADD2(wA0, ADD2(wA1, wA2)));
        den1 = ADD2(den1, ADD2(wB0, ADD2(wB1, wB2)));

        lds6(a, ra + CSTRIDE);
        wa0 = FMA2(wA0, PK(a[0], a[1]),
              FMA2(wA1, PK(a[1], a[2]),
              FMA2(wA2, PK(a[2], a[3]), wa0)));
        wa1 = FMA2(wB0, PK(a[2], a[3]),
              FMA2(wB1, PK(a[3], a[4]),
              FMA2(wB2, PK(a[4], a[5]), wa1)));

        lds6(b, ra + 2 * CSTRIDE);
        wb0 = FMA2(wA0, PK(b[0], b[1]),
              FMA2(wA1, PK(b[1], b[2]),
              FMA2(wA2, PK(b[2], b[3]), wb0)));
        wb1 = FMA2(wB0, PK(b[2], b[3]),
              FMA2(wB1, PK(b[3], b[4]),
              FMA2(wB2, PK(b[4], b[5]), wb1)));
    }

    // ---- epilogue: rcp + packed scale, float4 stores ----
    float d0, d1, d2, d3;
    UPK(d0, d1, den0);
    UPK(d2, d3, den1);
    u64 iv0 = PK(RCP(d0), RCP(d1));
    u64 iv1 = PK(RCP(d2), RCP(d3));

    u64 oa0 = MUL2(wa0, iv0), oa1 = MUL2(wa1, iv1);
    u64 ob0 = MUL2(wb0, iv0), ob1 = MUL2(wb1, iv1);

    float4 oa, ob;
    UPK(oa.x, oa.y, oa0); UPK(oa.z, oa.w, oa1);
    UPK(ob.x, ob.y, ob0); UPK(ob.z, ob.w, ob1);

    float* outp = out + n * 2 * PLANE + (y0 + ty) * W + x0 + 4 * tx;
    *(float4*)outp          = oa;
    *(float4*)(outp + PLANE) = ob;
}

extern "C" void kernel_launch(void* const* d_in, const int* in_sizes, int n_in,
                              void* d_out, int out_size)
{
    const float* x = (const float*)d_in[0];
    float* out = (float*)d_out;
    int N = in_sizes[0] / (3 * H * W);   // 16

    dim3 block(TX, TY);
    dim3 grid(W / TILE_W, H / TILE_H, N);
    wavg_kernel<<<grid, block>>>(x, out);
}

// round 16
// speedup vs baseline: 1.0376x; 1.0376x over previous
#include <cuda_runtime.h>
#include <cuda_bf16.h>

// WeightedAverage: 3x3 local softmax over L-channel diffs, weighted average
// of a/b channels. x_lab [N,3,512,512] fp32 -> out [N,2,512,512] fp32.
//
// R16: no shared memory, no barriers. Each thread loads its 3x6 window rows
// directly from global (aligned LDG.128 + 2 predicated edge scalars per
// row-channel); input is L2/L1-resident so latency is low and warps run
// fully independently. Zero-fill for out-of-image rows/cols reproduces the
// reference's zero padding. FP core: symmetric center-row exps (5 not 8),
// packed FFMA2 accumulate chains, EX2/RCP fast math.

#define H 512
#define W 512
#define TX 32
#define TY 8
#define TILE_W 128
#define TILE_H 8
#define PLANE (H * W)

typedef unsigned long long u64;
typedef unsigned int u32;

__device__ __forceinline__ u64 PK(float lo, float hi) {
    u64 r; asm("mov.b64 %0,{%1,%2};" : "=l"(r) : "f"(lo), "f"(hi)); return r;
}
__device__ __forceinline__ void UPK(float& lo, float& hi, u64 v) {
    asm("mov.b64 {%0,%1},%2;" : "=f"(lo), "=f"(hi) : "l"(v));
}
__device__ __forceinline__ u64 ADD2(u64 a, u64 b) {
    u64 r; asm("add.rn.f32x2 %0,%1,%2;" : "=l"(r) : "l"(a), "l"(b)); return r;
}
__device__ __forceinline__ u64 MUL2(u64 a, u64 b) {
    u64 r; asm("mul.rn.f32x2 %0,%1,%2;" : "=l"(r) : "l"(a), "l"(b)); return r;
}
__device__ __forceinline__ u64 FMA2(u64 a, u64 b, u64 c) {
    u64 r; asm("fma.rn.f32x2 %0,%1,%2,%3;" : "=l"(r) : "l"(a), "l"(b), "l"(c)); return r;
}
__device__ __forceinline__ float EX2(float x) {
    float r; asm("ex2.approx.f32 %0,%1;" : "=f"(r) : "f"(x)); return r;
}
__device__ __forceinline__ float RCP(float x) {
    float r; asm("rcp.approx.f32 %0,%1;" : "=f"(r) : "f"(x)); return r;
}
__device__ __forceinline__ float WGT(float l, float lc) {
    float d = l - lc;
    return EX2(d * d * (-1.4426950408889634f));
}

// load window cols X-1..X+4 of one global row into d[0..5]; zero OOB cols
__device__ __forceinline__ void gload6(float* d, const float* __restrict__ rowp,
                                       int X, bool plo, bool phi) {
    float4 m = *(const float4*)(rowp + X);     // X aligned to 16B
    float lf = 0.f, rt = 0.f;
    if (plo) lf = __ldg(rowp + X - 1);
    if (phi) rt = __ldg(rowp + X + 4);
    d[0] = lf;  d[1] = m.x; d[2] = m.y;
    d[3] = m.z; d[4] = m.w; d[5] = rt;
}

__global__ __launch_bounds__(256, 5) void wavg_kernel(
    const float* __restrict__ x, float* __restrict__ out)
{
    const int tx = threadIdx.x, ty = threadIdx.y;
    const int n  = blockIdx.z;
    const int x0 = blockIdx.x * TILE_W;
    const int y0 = blockIdx.y * TILE_H;
    const int X  = x0 + 4 * tx;          // first output col of this thread
    const int gy = y0 + ty;              // output row

    const bool plo = (X >= 1);           // col X-1 in range
    const bool phi = (X <= W - 5);       // col X+4 in range
    const bool yup = (gy >= 1);
    const bool ydn = (gy <= H - 2);

    const float* Lr = x + n * 3 * PLANE + gy * W;   // L channel, center row
    const float* Ar = Lr + PLANE;
    const float* Br = Lr + 2 * PLANE;

    float l[6], a[6], b[6];
    u64 den0, den1, wa0, wa1, wb0, wb1;
    float lc0, lc1, lc2, lc3;

    // ---- center row: lc + free center tap + symmetric adjacent exps ----
    {
        gload6(l, Lr, X, plo, phi);
        lc0 = l[1]; lc1 = l[2]; lc2 = l[3]; lc3 = l[4];
        float e0 = WGT(l[0], l[1]);
        float e1 = WGT(l[1], l[2]);
        float e2 = WGT(l[2], l[3]);
        float e3 = WGT(l[3], l[4]);
        float e4 = WGT(l[4], l[5]);
        u64 wL0 = PK(e0, e1), wR0 = PK(e1, e2);   // px(0,1): left,right taps
        u64 wL1 = PK(e2, e3), wR1 = PK(e3, e4);   // px(2,3)
        const u64 one2 = PK(1.0f, 1.0f);
        den0 = ADD2(one2, ADD2(wL0, wR0));
        den1 = ADD2(one2, ADD2(wL1, wR1));

        gload6(a, Ar, X, plo, phi);
        wa0 = FMA2(wL0, PK(a[0], a[1]), FMA2(wR0, PK(a[2], a[3]), PK(a[1], a[2])));
        wa1 = FMA2(wL1, PK(a[2], a[3]), FMA2(wR1, PK(a[4], a[5]), PK(a[3], a[4])));

        gload6(b, Br, X, plo, phi);
        wb0 = FMA2(wL0, PK(b[0], b[1]), FMA2(wR0, PK(b[2], b[3]), PK(b[1], b[2])));
        wb1 = FMA2(wL1, PK(b[2], b[3]), FMA2(wR1, PK(b[4], b[5]), PK(b[3], b[4])));
    }

    // ---- rows above (dy=-1) and below (dy=+1): full 3 taps ----
    #pragma unroll
    for (int s = 0; s < 2; s++) {
        const int doff = s ? W : -W;
        const bool yv  = s ? ydn : yup;
        if (yv) {
            gload6(l, Lr + doff, X, plo, phi);
            gload6(a, Ar + doff, X, plo, phi);
            gload6(b, Br + doff, X, plo, phi);
        } else {
            #pragma unroll
            for (int t = 0; t < 6; t++) { l[t] = 0.f; a[t] = 0.f; b[t] = 0.f; }
        }
        float e00 = WGT(l[0], lc0), e10 = WGT(l[1], lc1);
        float e20 = WGT(l[2], lc2), e30 = WGT(l[3], lc3);
        float e01 = WGT(l[1], lc0), e11 = WGT(l[2], lc1);
        float e21 = WGT(l[3], lc2), e31 = WGT(l[4], lc3);
        float e02 = WGT(l[2], lc0), e12 = WGT(l[3], lc1);
        float e22 = WGT(l[4], lc2), e32 = WGT(l[5], lc3);
        u64 wA0 = PK(e00, e10), wA1 = PK(e01, e11), wA2 = PK(e02, e12);
        u64 wB0 = PK(e20, e30), wB1 = PK(e21, e31), wB2 = PK(e22, e32);
        den0 = ADD2(den0, ADD2(wA0, ADD2(wA1, wA2)));
        den1 = ADD2(den1, ADD2(wB0, ADD2(wB1, wB2)));

        wa0 = FMA2(wA0, PK(a[0], a[1]),
              FMA2(wA1, PK(a[1], a[2]),
              FMA2(wA2, PK(a[2], a[3]), wa0)));
        wa1 = FMA2(wB0, PK(a[2], a[3]),
              FMA2(wB1, PK(a[3], a[4]),
              FMA2(wB2, PK(a[4], a[5]), wa1)));

        wb0 = FMA2(wA0, PK(b[0], b[1]),
              FMA2(wA1, PK(b[1], b[2]),
              FMA2(wA2, PK(b[2], b[3]), wb0)));
        wb1 = FMA2(wB0, PK(b[2], b[3]),
              FMA2(wB1, PK(b[3], b[4]),
              FMA2(wB2, PK(b[4], b[5]), wb1)));
    }

    // ---- epilogue: rcp + packed scale, float4 stores ----
    float d0, d1, d2, d3;
    UPK(d0, d1, den0);
    UPK(d2, d3, den1);
    u64 iv0 = PK(RCP(d0), RCP(d1));
    u64 iv1 = PK(RCP(d2), RCP(d3));

    u64 oa0 = MUL2(wa0, iv0), oa1 = MUL2(wa1, iv1);
    u64 ob0 = MUL2(wb0, iv0), ob1 = MUL2(wb1, iv1);

    float4 oa, ob;
    UPK(oa.x, oa.y, oa0); UPK(oa.z, oa.w, oa1);
    UPK(ob.x, ob.y, ob0); UPK(ob.z, ob.w, ob1);

    float* outp = out + n * 2 * PLANE + gy * W + X;
    *(float4*)outp           = oa;
    *(float4*)(outp + PLANE) = ob;
}

extern "C" void kernel_launch(void* const* d_in, const int* in_sizes, int n_in,
                              void* d_out, int out_size)
{
    const float* x = (const float*)d_in[0];
    float* out = (float*)d_out;
    int N = in_sizes[0] / (3 * H * W);   // 16

    dim3 block(TX, TY);
    dim3 grid(W / TILE_W, H / TILE_H, N);
    wavg_kernel<<<grid, block>>>(x, out);
}

// round 17
// speedup vs baseline: 1.1892x; 1.1460x over previous
#include <cuda_runtime.h>
#include <cuda_bf16.h>

// WeightedAverage: 3x3 local softmax over L-channel diffs, weighted average
// of a/b channels. x_lab [N,3,512,512] fp32 -> out [N,2,512,512] fp32.
//
// R17: edge columns via warp shuffle instead of scalar LDGs. Each thread
// loads one aligned LDG.128 per row-channel; left/right window edges come
// from neighbor lanes' registers (shfl.up/down), lanes 0/31 use a 1-lane
// predicated LDG. Cuts L1 wavefronts ~2x vs R16. No smem, no barriers.
// FP core unchanged: symmetric center-row exps, FFMA2 accumulate chains.

#define H 512
#define W 512
#define TX 32
#define TY 8
#define TILE_W 128
#define TILE_H 8
#define PLANE (H * W)

typedef unsigned long long u64;
typedef unsigned int u32;

__device__ __forceinline__ u64 PK(float lo, float hi) {
    u64 r; asm("mov.b64 %0,{%1,%2};" : "=l"(r) : "f"(lo), "f"(hi)); return r;
}
__device__ __forceinline__ void UPK(float& lo, float& hi, u64 v) {
    asm("mov.b64 {%0,%1},%2;" : "=f"(lo), "=f"(hi) : "l"(v));
}
__device__ __forceinline__ u64 ADD2(u64 a, u64 b) {
    u64 r; asm("add.rn.f32x2 %0,%1,%2;" : "=l"(r) : "l"(a), "l"(b)); return r;
}
__device__ __forceinline__ u64 MUL2(u64 a, u64 b) {
    u64 r; asm("mul.rn.f32x2 %0,%1,%2;" : "=l"(r) : "l"(a), "l"(b)); return r;
}
__device__ __forceinline__ u64 FMA2(u64 a, u64 b, u64 c) {
    u64 r; asm("fma.rn.f32x2 %0,%1,%2,%3;" : "=l"(r) : "l"(a), "l"(b), "l"(c)); return r;
}
__device__ __forceinline__ float EX2(float x) {
    float r; asm("ex2.approx.f32 %0,%1;" : "=f"(r) : "f"(x)); return r;
}
__device__ __forceinline__ float RCP(float x) {
    float r; asm("rcp.approx.f32 %0,%1;" : "=f"(r) : "f"(x)); return r;
}
__device__ __forceinline__ float WGT(float l, float lc) {
    float d = l - lc;
    return EX2(d * d * (-1.4426950408889634f));
}

// window cols X-1..X+4 of one global row: 1 LDG.128 + 2 shuffles
// (+1-lane predicated LDGs at the warp boundary lanes)
__device__ __forceinline__ void row6(float* d, const float* __restrict__ rowp,
                                     int X, int lane, bool lok, bool rok) {
    float4 m = *(const float4*)(rowp + X);
    float lf = __shfl_up_sync(0xffffffffu, m.w, 1);
    float rt = __shfl_down_sync(0xffffffffu, m.x, 1);
    if (lane == 0)  lf = lok ? __ldg(rowp + X - 1) : 0.f;
    if (lane == 31) rt = rok ? __ldg(rowp + X + 4) : 0.f;
    d[0] = lf;  d[1] = m.x; d[2] = m.y;
    d[3] = m.z; d[4] = m.w; d[5] = rt;
}

__global__ __launch_bounds__(256, 5) void wavg_kernel(
    const float* __restrict__ x, float* __restrict__ out)
{
    const int tx = threadIdx.x, ty = threadIdx.y;
    const int n  = blockIdx.z;
    const int x0 = blockIdx.x * TILE_W;
    const int y0 = blockIdx.y * TILE_H;
    const int X  = x0 + 4 * tx;          // first output col of this thread
    const int gy = y0 + ty;              // output row (warp-uniform)

    const bool lok = (x0 > 0);               // warp-boundary left col exists
    const bool rok = (x0 + TILE_W < W);      // warp-boundary right col exists
    const bool yup = (gy >= 1);              // warp-uniform
    const bool ydn = (gy <= H - 2);          // warp-uniform

    const float* Lr = x + n * 3 * PLANE + gy * W;   // L channel, center row
    const float* Ar = Lr + PLANE;
    const float* Br = Lr + 2 * PLANE;

    float l[6], a[6], b[6];
    u64 den0, den1, wa0, wa1, wb0, wb1;
    float lc0, lc1, lc2, lc3;

    // ---- center row: lc + free center tap + symmetric adjacent exps ----
    {
        row6(l, Lr, X, tx, lok, rok);
        lc0 = l[1]; lc1 = l[2]; lc2 = l[3]; lc3 = l[4];
        float e0 = WGT(l[0], l[1]);
        float e1 = WGT(l[1], l[2]);
        float e2 = WGT(l[2], l[3]);
        float e3 = WGT(l[3], l[4]);
        float e4 = WGT(l[4], l[5]);
        u64 wL0 = PK(e0, e1), wR0 = PK(e1, e2);   // px(0,1): left,right taps
        u64 wL1 = PK(e2, e3), wR1 = PK(e3, e4);   // px(2,3)
        const u64 one2 = PK(1.0f, 1.0f);
        den0 = ADD2(one2, ADD2(wL0, wR0));
        den1 = ADD2(one2, ADD2(wL1, wR1));

        row6(a, Ar, X, tx, lok, rok);
        wa0 = FMA2(wL0, PK(a[0], a[1]), FMA2(wR0, PK(a[2], a[3]), PK(a[1], a[2])));
        wa1 = FMA2(wL1, PK(a[2], a[3]), FMA2(wR1, PK(a[4], a[5]), PK(a[3], a[4])));

        row6(b, Br, X, tx, lok, rok);
        wb0 = FMA2(wL0, PK(b[0], b[1]), FMA2(wR0, PK(b[2], b[3]), PK(b[1], b[2])));
        wb1 = FMA2(wL1, PK(b[2], b[3]), FMA2(wR1, PK(b[4], b[5]), PK(b[3], b[4])));
    }

    // ---- rows above (dy=-1) and below (dy=+1): full 3 taps ----
    #pragma unroll
    for (int s = 0; s < 2; s++) {
        const int doff = s ? W : -W;
        const bool yv  = s ? ydn : yup;      // warp-uniform branch: shfl-safe
        if (yv) {
            row6(l, Lr + doff, X, tx, lok, rok);
            row6(a, Ar + doff, X, tx, lok, rok);
            row6(b, Br + doff, X, tx, lok, rok);
        } else {
            #pragma unroll
            for (int t = 0; t < 6; t++) { l[t] = 0.f; a[t] = 0.f; b[t] = 0.f; }
        }
        float e00 = WGT(l[0], lc0), e10 = WGT(l[1], lc1);
        float e20 = WGT(l[2], lc2), e30 = WGT(l[3], lc3);
        float e01 = WGT(l[1], lc0), e11 = WGT(l[2], lc1);
        float e21 = WGT(l[3], lc2), e31 = WGT(l[4], lc3);
        float e02 = WGT(l[2], lc0), e12 = WGT(l[3], lc1);
        float e22 = WGT(l[4], lc2), e32 = WGT(l[5], lc3);
        u64 wA0 = PK(e00, e10), wA1 = PK(e01, e11), wA2 = PK(e02, e12);
        u64 wB0 = PK(e20, e30), wB1 = PK(e21, e31), wB2 = PK(e22, e32);
        den0 = ADD2(den0, ADD2(wA0, ADD2(wA1, wA2)));
        den1 = ADD2(den1, ADD2(wB0, ADD2(wB1, wB2)));

        wa0 = FMA2(wA0, PK(a[0], a[1]),
              FMA2(wA1, PK(a[1], a[2]),
              FMA2(wA2, PK(a[2], a[3]), wa0)));
        wa1 = FMA2(wB0, PK(a[2], a[3]),
              FMA2(wB1, PK(a[3], a[4]),
              FMA2(wB2, PK(a[4], a[5]), wa1)));

        wb0 = FMA2(wA0, PK(b[0], b[1]),
              FMA2(wA1, PK(b[1], b[2]),
              FMA2(wA2, PK(b[2], b[3]), wb0)));
        wb1 = FMA2(wB0, PK(b[2], b[3]),
              FMA2(wB1, PK(b[3], b[4]),
              FMA2(wB2, PK(b[4], b[5]), wb1)));
    }

    // ---- epilogue: rcp + packed scale, float4 stores ----
    float d0, d1, d2, d3;
    UPK(d0, d1, den0);
    UPK(d2, d3, den1);
    u64 iv0 = PK(RCP(d0), RCP(d1));
    u64 iv1 = PK(RCP(d2), RCP(d3));

    u64 oa0 = MUL2(wa0, iv0), oa1 = MUL2(wa1, iv1);
    u64 ob0 = MUL2(wb0, iv0), ob1 = MUL2(wb1, iv1);

    float4 oa, ob;
    UPK(oa.x, oa.y, oa0); UPK(oa.z, oa.w, oa1);
    UPK(ob.x, ob.y, ob0); UPK(ob.z, ob.w, ob1);

    float* outp = out + n * 2 * PLANE + gy * W + X;
    *(float4*)outp           = oa;
    *(float4*)(outp + PLANE) = ob;
}

extern "C" void kernel_launch(void* const* d_in, const int* in_sizes, int n_in,
                              void* d_out, int out_size)
{
    const float* x = (const float*)d_in[0];
    float* out = (float*)d_out;
    int N = in_sizes[0] / (3 * H * W);   // 16

    dim3 block(TX, TY);
    dim3 grid(W / TILE_W, H / TILE_H, N);
    wavg_kernel<<<grid, block>>>(x, out);
}